// round 4
// baseline (speedup 1.0000x reference)
#include <cuda_runtime.h>
#include <math.h>

#define BB 2048
#define TT 2048
#define CC 8
#define AA 27
#define HH 8

__device__ __forceinline__ float tanh_approx(float v) {
    float r;
    asm("tanh.approx.f32 %0, %1;" : "=f"(r) : "f"(v));
    return r;
}

// Fused: per-row MLP (computed redundantly per block, hidden under x-load
// latency) + streaming channel contraction + ELU.
// Grid: BB * (TT/512) blocks of 256 threads; each thread produces 2 outputs.
__global__ void __launch_bounds__(256) fused_kernel(
    const float* __restrict__ x,
    const float* __restrict__ attrs,
    const float* __restrict__ w1,  const float* __restrict__ b1,
    const float* __restrict__ w2,  const float* __restrict__ b2,
    const float* __restrict__ bw1, const float* __restrict__ bb1,
    const float* __restrict__ bw2, const float* __restrict__ bb2,
    const float* __restrict__ mask_a,
    const float* __restrict__ mask_h,
    float* __restrict__ out)
{
    int b  = blockIdx.x >> 2;                        // 4 blocks per batch row
    int t0 = ((blockIdx.x & 3) << 9) + threadIdx.x;  // this thread: t0, t0+256

    // ---- issue the x loads first (independent of the MLP) ----
    const float4* xp0 = (const float4*)(x + ((long)b * TT + t0) * CC);
    const float4* xp1 = (const float4*)(x + ((long)b * TT + t0 + 256) * CC);
    float4 xa0 = xp0[0], xa1 = xp0[1];
    float4 xb0 = xp1[0], xb1 = xp1[1];

    // ---- per-row MLP, replicated across threads (broadcast loads) ----
    float hw[HH], hb[HH];
#pragma unroll
    for (int h = 0; h < HH; h++) { hw[h] = b1[h]; hb[h] = bb1[h]; }

#pragma unroll
    for (int i = 0; i < AA; i++) {
        float ai = attrs[b * AA + i] * mask_a[b * AA + i];
#pragma unroll
        for (int h = 0; h < HH; h++) {
            hw[h] = fmaf(ai, w1[i * HH + h], hw[h]);
            hb[h] = fmaf(ai, bw1[i * HH + h], hb[h]);
        }
    }

#pragma unroll
    for (int h = 0; h < HH; h++) {
        float m = mask_h[b * HH + h];
        hw[h] = fmaxf(hw[h], 0.0f) * m;
        hb[h] = fmaxf(hb[h], 0.0f) * m;
    }

    float k[CC];
#pragma unroll
    for (int c = 0; c < CC; c++) {
        float s = b2[c];
#pragma unroll
        for (int h = 0; h < HH; h++)
            s = fmaf(hw[h], w2[h * CC + c], s);
        k[c] = tanh_approx(s);
    }

    float bias = bb2[0];
#pragma unroll
    for (int h = 0; h < HH; h++)
        bias = fmaf(hb[h], bw2[h], bias);
    bias = tanh_approx(bias);

    // ---- contraction + ELU for both t's ----
    float ya = bias;
    ya = fmaf(xa0.x, k[0], ya); ya = fmaf(xa0.y, k[1], ya);
    ya = fmaf(xa0.z, k[2], ya); ya = fmaf(xa0.w, k[3], ya);
    ya = fmaf(xa1.x, k[4], ya); ya = fmaf(xa1.y, k[5], ya);
    ya = fmaf(xa1.z, k[6], ya); ya = fmaf(xa1.w, k[7], ya);

    float yb = bias;
    yb = fmaf(xb0.x, k[0], yb); yb = fmaf(xb0.y, k[1], yb);
    yb = fmaf(xb0.z, k[2], yb); yb = fmaf(xb0.w, k[3], yb);
    yb = fmaf(xb1.x, k[4], yb); yb = fmaf(xb1.y, k[5], yb);
    yb = fmaf(xb1.z, k[6], yb); yb = fmaf(xb1.w, k[7], yb);

    float ra = (ya > 0.0f) ? ya : expm1f(ya);
    float rb = (yb > 0.0f) ? yb : expm1f(yb);

    long base = (long)b * TT + t0;
    out[base]       = ra;
    out[base + 256] = rb;
}

extern "C" void kernel_launch(void* const* d_in, const int* in_sizes, int n_in,
                              void* d_out, int out_size) {
    const float* x      = (const float*)d_in[0];
    const float* attrs  = (const float*)d_in[1];
    const float* w1     = (const float*)d_in[2];
    const float* b1     = (const float*)d_in[3];
    const float* w2     = (const float*)d_in[4];
    const float* b2     = (const float*)d_in[5];
    const float* bw1    = (const float*)d_in[6];
    const float* bb1    = (const float*)d_in[7];
    const float* bw2    = (const float*)d_in[8];
    const float* bb2    = (const float*)d_in[9];
    const float* mask_a = (const float*)d_in[10];
    const float* mask_h = (const float*)d_in[11];
    float* out = (float*)d_out;

    fused_kernel<<<BB * (TT / 512), 256>>>(x, attrs, w1, b1, w2, b2,
                                           bw1, bb1, bw2, bb2,
                                           mask_a, mask_h, out);
}

// round 8
// speedup vs baseline: 2.3737x; 2.3737x over previous
#include <cuda_runtime.h>
#include <math.h>

#define BB 2048
#define TT 2048
#define CC 8
#define AA 27
#define HH 8

__device__ __forceinline__ float tanh_approx(float v) {
    float r;
    asm("tanh.approx.f32 %0, %1;" : "=f"(r) : "f"(v));
    return r;
}

// Fused: per-row MLP computed ONCE per block by thread 0 into smem
// (overlapped with the x-load stream of the other 255 threads),
// then streaming channel contraction + ELU.
// Grid: BB * (TT/512) blocks of 256 threads; each thread produces 2 outputs.
__global__ void __launch_bounds__(256) fused_kernel(
    const float* __restrict__ x,
    const float* __restrict__ attrs,
    const float* __restrict__ w1,  const float* __restrict__ b1,
    const float* __restrict__ w2,  const float* __restrict__ b2,
    const float* __restrict__ bw1, const float* __restrict__ bb1,
    const float* __restrict__ bw2, const float* __restrict__ bb2,
    const float* __restrict__ mask_a,
    const float* __restrict__ mask_h,
    float* __restrict__ out)
{
    __shared__ float sk[CC];
    __shared__ float sbias;

    int b  = blockIdx.x >> 2;                        // 4 blocks per batch row
    int t0 = ((blockIdx.x & 3) << 9) + threadIdx.x;  // this thread: t0, t0+256

    // ---- issue the x loads first (independent of the MLP, kept in regs
    //      across the barrier so DRAM streams while thread 0 computes) ----
    const float4* xp0 = (const float4*)(x + ((long)b * TT + t0) * CC);
    const float4* xp1 = (const float4*)(x + ((long)b * TT + t0 + 256) * CC);
    float4 xa0 = xp0[0], xa1 = xp0[1];
    float4 xb0 = xp1[0], xb1 = xp1[1];

    if (threadIdx.x == 0) {
        float hw[HH], hb[HH];
#pragma unroll
        for (int h = 0; h < HH; h++) { hw[h] = b1[h]; hb[h] = bb1[h]; }

#pragma unroll
        for (int i = 0; i < AA; i++) {
            float ai = attrs[b * AA + i] * mask_a[b * AA + i];
#pragma unroll
            for (int h = 0; h < HH; h++) {
                hw[h] = fmaf(ai, w1[i * HH + h], hw[h]);
                hb[h] = fmaf(ai, bw1[i * HH + h], hb[h]);
            }
        }

#pragma unroll
        for (int h = 0; h < HH; h++) {
            float m = mask_h[b * HH + h];
            hw[h] = fmaxf(hw[h], 0.0f) * m;
            hb[h] = fmaxf(hb[h], 0.0f) * m;
        }

#pragma unroll
        for (int c = 0; c < CC; c++) {
            float s = b2[c];
#pragma unroll
            for (int h = 0; h < HH; h++)
                s = fmaf(hw[h], w2[h * CC + c], s);
            sk[c] = tanh_approx(s);
        }

        float s = bb2[0];
#pragma unroll
        for (int h = 0; h < HH; h++)
            s = fmaf(hb[h], bw2[h], s);
        sbias = tanh_approx(s);
    }
    __syncthreads();

    float k0 = sk[0], k1 = sk[1], k2 = sk[2], k3 = sk[3];
    float k4 = sk[4], k5 = sk[5], k6 = sk[6], k7 = sk[7];
    float bias = sbias;

    float ya = bias;
    ya = fmaf(xa0.x, k0, ya); ya = fmaf(xa0.y, k1, ya);
    ya = fmaf(xa0.z, k2, ya); ya = fmaf(xa0.w, k3, ya);
    ya = fmaf(xa1.x, k4, ya); ya = fmaf(xa1.y, k5, ya);
    ya = fmaf(xa1.z, k6, ya); ya = fmaf(xa1.w, k7, ya);

    float yb = bias;
    yb = fmaf(xb0.x, k0, yb); yb = fmaf(xb0.y, k1, yb);
    yb = fmaf(xb0.z, k2, yb); yb = fmaf(xb0.w, k3, yb);
    yb = fmaf(xb1.x, k4, yb); yb = fmaf(xb1.y, k5, yb);
    yb = fmaf(xb1.z, k6, yb); yb = fmaf(xb1.w, k7, yb);

    float ra = (ya > 0.0f) ? ya : expm1f(ya);
    float rb = (yb > 0.0f) ? yb : expm1f(yb);

    long base = (long)b * TT + t0;
    out[base]       = ra;
    out[base + 256] = rb;
}

extern "C" void kernel_launch(void* const* d_in, const int* in_sizes, int n_in,
                              void* d_out, int out_size) {
    const float* x      = (const float*)d_in[0];
    const float* attrs  = (const float*)d_in[1];
    const float* w1     = (const float*)d_in[2];
    const float* b1     = (const float*)d_in[3];
    const float* w2     = (const float*)d_in[4];
    const float* b2     = (const float*)d_in[5];
    const float* bw1    = (const float*)d_in[6];
    const float* bb1    = (const float*)d_in[7];
    const float* bw2    = (const float*)d_in[8];
    const float* bb2    = (const float*)d_in[9];
    const float* mask_a = (const float*)d_in[10];
    const float* mask_h = (const float*)d_in[11];
    float* out = (float*)d_out;

    fused_kernel<<<BB * (TT / 512), 256>>>(x, attrs, w1, b1, w2, b2,
                                           bw1, bb1, bw2, bb2,
                                           mask_a, mask_h, out);
}

// round 9
// speedup vs baseline: 4.3956x; 1.8518x over previous
#include <cuda_runtime.h>
#include <math.h>

#define BB 2048
#define TT 2048
#define CC 8
#define AA 27
#define HH 8

__device__ __forceinline__ float tanh_approx(float v) {
    float r;
    asm("tanh.approx.f32 %0, %1;" : "=f"(r) : "f"(v));
    return r;
}

// Fused, barrier-free: each WARP cooperatively computes its row's MLP via
// shuffles (no smem, no __syncthreads), overlapped with the x-load stream.
// Grid: BB * (TT/512) blocks of 256 threads; each thread produces 2 outputs.
__global__ void __launch_bounds__(256) fused_kernel(
    const float* __restrict__ x,
    const float* __restrict__ attrs,
    const float* __restrict__ w1,  const float* __restrict__ b1,
    const float* __restrict__ w2,  const float* __restrict__ b2,
    const float* __restrict__ bw1, const float* __restrict__ bb1,
    const float* __restrict__ bw2, const float* __restrict__ bb2,
    const float* __restrict__ mask_a,
    const float* __restrict__ mask_h,
    float* __restrict__ out)
{
    int b  = blockIdx.x >> 2;                        // 4 blocks per batch row
    int t0 = ((blockIdx.x & 3) << 9) + threadIdx.x;  // this thread: t0, t0+256

    // ---- issue the x loads first (independent of the MLP) ----
    const float4* xp0 = (const float4*)(x + ((long)b * TT + t0) * CC);
    const float4* xp1 = (const float4*)(x + ((long)b * TT + t0 + 256) * CC);
    float4 xa0 = xp0[0], xa1 = xp0[1];
    float4 xb0 = xp1[0], xb1 = xp1[1];

    // ---- warp-cooperative MLP ----
    const unsigned FULL = 0xFFFFFFFFu;
    int lane = threadIdx.x & 31;
    int h = lane & 7;        // hidden unit handled by this lane
    int g = lane >> 3;       // i-group (0..3)

    float hw = 0.0f, hb = 0.0f;
#pragma unroll
    for (int s = 0; s < 7; s++) {
        int i = g + 4 * s;
        if (i < AA) {
            float ai = attrs[b * AA + i] * mask_a[b * AA + i];
            hw = fmaf(ai, w1[i * HH + h], hw);
            hb = fmaf(ai, bw1[i * HH + h], hb);
        }
    }
    // reduce partial sums across the 4 groups (lane bits 3,4)
    hw += __shfl_xor_sync(FULL, hw, 8);
    hw += __shfl_xor_sync(FULL, hw, 16);
    hb += __shfl_xor_sync(FULL, hb, 8);
    hb += __shfl_xor_sync(FULL, hb, 16);

    float m = mask_h[b * HH + h];
    hw = fmaxf(hw + b1[h], 0.0f) * m;
    hb = fmaxf(hb + bb1[h], 0.0f) * m;

    // layer 2: lane computes output channel c == h; bias acc is lane-uniform
    float kacc = b2[h];
    float bacc = bb2[0];
#pragma unroll
    for (int hh = 0; hh < 8; hh++) {
        float hwv = __shfl_sync(FULL, hw, hh);   // lane hh holds reduced hw[hh]
        float hbv = __shfl_sync(FULL, hb, hh);
        kacc = fmaf(hwv, w2[hh * CC + h], kacc);
        bacc = fmaf(hbv, bw2[hh], bacc);
    }
    float kc   = tanh_approx(kacc);
    float bias = tanh_approx(bacc);              // identical on every lane

    // broadcast k[0..7] to all lanes
    float k0 = __shfl_sync(FULL, kc, 0);
    float k1 = __shfl_sync(FULL, kc, 1);
    float k2 = __shfl_sync(FULL, kc, 2);
    float k3 = __shfl_sync(FULL, kc, 3);
    float k4 = __shfl_sync(FULL, kc, 4);
    float k5 = __shfl_sync(FULL, kc, 5);
    float k6 = __shfl_sync(FULL, kc, 6);
    float k7 = __shfl_sync(FULL, kc, 7);

    // ---- contraction + ELU for both t's ----
    float ya = bias;
    ya = fmaf(xa0.x, k0, ya); ya = fmaf(xa0.y, k1, ya);
    ya = fmaf(xa0.z, k2, ya); ya = fmaf(xa0.w, k3, ya);
    ya = fmaf(xa1.x, k4, ya); ya = fmaf(xa1.y, k5, ya);
    ya = fmaf(xa1.z, k6, ya); ya = fmaf(xa1.w, k7, ya);

    float yb = bias;
    yb = fmaf(xb0.x, k0, yb); yb = fmaf(xb0.y, k1, yb);
    yb = fmaf(xb0.z, k2, yb); yb = fmaf(xb0.w, k3, yb);
    yb = fmaf(xb1.x, k4, yb); yb = fmaf(xb1.y, k5, yb);
    yb = fmaf(xb1.z, k6, yb); yb = fmaf(xb1.w, k7, yb);

    float ra = (ya > 0.0f) ? ya : expm1f(ya);
    float rb = (yb > 0.0f) ? yb : expm1f(yb);

    long base = (long)b * TT + t0;
    out[base]       = ra;
    out[base + 256] = rb;
}

extern "C" void kernel_launch(void* const* d_in, const int* in_sizes, int n_in,
                              void* d_out, int out_size) {
    const float* x      = (const float*)d_in[0];
    const float* attrs  = (const float*)d_in[1];
    const float* w1     = (const float*)d_in[2];
    const float* b1     = (const float*)d_in[3];
    const float* w2     = (const float*)d_in[4];
    const float* b2     = (const float*)d_in[5];
    const float* bw1    = (const float*)d_in[6];
    const float* bb1    = (const float*)d_in[7];
    const float* bw2    = (const float*)d_in[8];
    const float* bb2    = (const float*)d_in[9];
    const float* mask_a = (const float*)d_in[10];
    const float* mask_h = (const float*)d_in[11];
    float* out = (float*)d_out;

    fused_kernel<<<BB * (TT / 512), 256>>>(x, attrs, w1, b1, w2, b2,
                                           bw1, bb1, bw2, bb2,
                                           mask_a, mask_h, out);
}

// round 10
// speedup vs baseline: 4.4600x; 1.0146x over previous
#include <cuda_runtime.h>
#include <math.h>

#define BB 2048
#define TT 2048
#define CC 8
#define AA 27
#define HH 8

__device__ __forceinline__ float tanh_approx(float v) {
    float r;
    asm("tanh.approx.f32 %0, %1;" : "=f"(r) : "f"(v));
    return r;
}

__device__ __forceinline__ float elu(float y) {
    return (y > 0.0f) ? y : expm1f(y);
}

// Fused, barrier-free. One block per batch row; each thread produces 8 outputs
// (t = tid + 256*j). The per-row MLP is computed warp-cooperatively via
// shuffles, amortized over 8x more data than R9 to unload the L1/MIO pipe.
__global__ void __launch_bounds__(256) fused_kernel(
    const float* __restrict__ x,
    const float* __restrict__ attrs,
    const float* __restrict__ w1,  const float* __restrict__ b1,
    const float* __restrict__ w2,  const float* __restrict__ b2,
    const float* __restrict__ bw1, const float* __restrict__ bb1,
    const float* __restrict__ bw2, const float* __restrict__ bb2,
    const float* __restrict__ mask_a,
    const float* __restrict__ mask_h,
    float* __restrict__ out)
{
    int b   = blockIdx.x;
    int tid = threadIdx.x;

    const float4* xrow = (const float4*)(x + (long)b * TT * CC);

    // ---- prefetch first two t's before the MLP (independent work) ----
    int t0 = tid, t1 = tid + 256;
    float4 p0a = xrow[t0 * 2], p0b = xrow[t0 * 2 + 1];
    float4 p1a = xrow[t1 * 2], p1b = xrow[t1 * 2 + 1];

    // ---- warp-cooperative MLP (no smem, no __syncthreads) ----
    const unsigned FULL = 0xFFFFFFFFu;
    int lane = tid & 31;
    int h = lane & 7;        // hidden unit handled by this lane
    int g = lane >> 3;       // i-group (0..3)

    float hw = 0.0f, hb = 0.0f;
#pragma unroll
    for (int s = 0; s < 7; s++) {
        int i = g + 4 * s;
        if (i < AA) {
            float ai = attrs[b * AA + i] * mask_a[b * AA + i];
            hw = fmaf(ai, w1[i * HH + h], hw);
            hb = fmaf(ai, bw1[i * HH + h], hb);
        }
    }
    hw += __shfl_xor_sync(FULL, hw, 8);
    hw += __shfl_xor_sync(FULL, hw, 16);
    hb += __shfl_xor_sync(FULL, hb, 8);
    hb += __shfl_xor_sync(FULL, hb, 16);

    float m = mask_h[b * HH + h];
    hw = fmaxf(hw + b1[h], 0.0f) * m;
    hb = fmaxf(hb + bb1[h], 0.0f) * m;

    float kacc = b2[h];
    float bacc = bb2[0];
#pragma unroll
    for (int hh = 0; hh < 8; hh++) {
        float hwv = __shfl_sync(FULL, hw, hh);
        float hbv = __shfl_sync(FULL, hb, hh);
        kacc = fmaf(hwv, w2[hh * CC + h], kacc);
        bacc = fmaf(hbv, bw2[hh], bacc);
    }
    float kc   = tanh_approx(kacc);
    float bias = tanh_approx(bacc);          // lane-uniform

    float k0 = __shfl_sync(FULL, kc, 0);
    float k1 = __shfl_sync(FULL, kc, 1);
    float k2 = __shfl_sync(FULL, kc, 2);
    float k3 = __shfl_sync(FULL, kc, 3);
    float k4 = __shfl_sync(FULL, kc, 4);
    float k5 = __shfl_sync(FULL, kc, 5);
    float k6 = __shfl_sync(FULL, kc, 6);
    float k7 = __shfl_sync(FULL, kc, 7);

    float* orow = out + (long)b * TT;

    // ---- pipelined contraction: compute pair j while loading pair j+2 ----
#pragma unroll
    for (int j = 0; j < 8; j += 2) {
        float4 n0a, n0b, n1a, n1b;
        if (j + 2 < 8) {
            int u0 = tid + 256 * (j + 2);
            int u1 = tid + 256 * (j + 3);
            n0a = xrow[u0 * 2]; n0b = xrow[u0 * 2 + 1];
            n1a = xrow[u1 * 2]; n1b = xrow[u1 * 2 + 1];
        }

        float ya = bias;
        ya = fmaf(p0a.x, k0, ya); ya = fmaf(p0a.y, k1, ya);
        ya = fmaf(p0a.z, k2, ya); ya = fmaf(p0a.w, k3, ya);
        ya = fmaf(p0b.x, k4, ya); ya = fmaf(p0b.y, k5, ya);
        ya = fmaf(p0b.z, k6, ya); ya = fmaf(p0b.w, k7, ya);

        float yb = bias;
        yb = fmaf(p1a.x, k0, yb); yb = fmaf(p1a.y, k1, yb);
        yb = fmaf(p1a.z, k2, yb); yb = fmaf(p1a.w, k3, yb);
        yb = fmaf(p1b.x, k4, yb); yb = fmaf(p1b.y, k5, yb);
        yb = fmaf(p1b.z, k6, yb); yb = fmaf(p1b.w, k7, yb);

        orow[tid + 256 * j]       = elu(ya);
        orow[tid + 256 * (j + 1)] = elu(yb);

        p0a = n0a; p0b = n0b;
        p1a = n1a; p1b = n1b;
    }
}

extern "C" void kernel_launch(void* const* d_in, const int* in_sizes, int n_in,
                              void* d_out, int out_size) {
    const float* x      = (const float*)d_in[0];
    const float* attrs  = (const float*)d_in[1];
    const float* w1     = (const float*)d_in[2];
    const float* b1     = (const float*)d_in[3];
    const float* w2     = (const float*)d_in[4];
    const float* b2     = (const float*)d_in[5];
    const float* bw1    = (const float*)d_in[6];
    const float* bb1    = (const float*)d_in[7];
    const float* bw2    = (const float*)d_in[8];
    const float* bb2    = (const float*)d_in[9];
    const float* mask_a = (const float*)d_in[10];
    const float* mask_h = (const float*)d_in[11];
    float* out = (float*)d_out;

    fused_kernel<<<BB, 256>>>(x, attrs, w1, b1, w2, b2,
                              bw1, bb1, bw2, bb2,
                              mask_a, mask_h, out);
}

// round 11
// speedup vs baseline: 5.0077x; 1.1228x over previous
#include <cuda_runtime.h>
#include <math.h>

#define BB 2048
#define TT 2048
#define CC 8
#define AA 27
#define HH 8

__device__ __forceinline__ float tanh_approx(float v) {
    float r;
    asm("tanh.approx.f32 %0, %1;" : "=f"(r) : "f"(v));
    return r;
}

__device__ __forceinline__ float elu(float y) {
    return (y > 0.0f) ? y : expm1f(y);
}

// Fused, barrier-free. One block of 128 threads per batch row; each thread
// produces 16 outputs (t = tid + 128*j). Per-row MLP is computed
// warp-cooperatively (4 instances/row). Pair-ahead software pipeline keeps
// 4 LDG.128 in flight per thread.
__global__ void __launch_bounds__(128) fused_kernel(
    const float* __restrict__ x,
    const float* __restrict__ attrs,
    const float* __restrict__ w1,  const float* __restrict__ b1,
    const float* __restrict__ w2,  const float* __restrict__ b2,
    const float* __restrict__ bw1, const float* __restrict__ bb1,
    const float* __restrict__ bw2, const float* __restrict__ bb2,
    const float* __restrict__ mask_a,
    const float* __restrict__ mask_h,
    float* __restrict__ out)
{
    int b   = blockIdx.x;
    int tid = threadIdx.x;

    const float4* xrow = (const float4*)(x + (long)b * TT * CC);

    // ---- prefetch first two t's before the MLP (independent work) ----
    float4 p0a = __ldcs(&xrow[tid * 2]);
    float4 p0b = __ldcs(&xrow[tid * 2 + 1]);
    float4 p1a = __ldcs(&xrow[(tid + 128) * 2]);
    float4 p1b = __ldcs(&xrow[(tid + 128) * 2 + 1]);

    // ---- warp-cooperative MLP (no smem, no __syncthreads) ----
    const unsigned FULL = 0xFFFFFFFFu;
    int lane = tid & 31;
    int h = lane & 7;        // hidden unit handled by this lane
    int g = lane >> 3;       // i-group (0..3)

    float hw = 0.0f, hb = 0.0f;
#pragma unroll
    for (int s = 0; s < 7; s++) {
        int i = g + 4 * s;
        if (i < AA) {
            float ai = attrs[b * AA + i] * mask_a[b * AA + i];
            hw = fmaf(ai, w1[i * HH + h], hw);
            hb = fmaf(ai, bw1[i * HH + h], hb);
        }
    }
    hw += __shfl_xor_sync(FULL, hw, 8);
    hw += __shfl_xor_sync(FULL, hw, 16);
    hb += __shfl_xor_sync(FULL, hb, 8);
    hb += __shfl_xor_sync(FULL, hb, 16);

    float m = mask_h[b * HH + h];
    hw = fmaxf(hw + b1[h], 0.0f) * m;
    hb = fmaxf(hb + bb1[h], 0.0f) * m;

    float kacc = b2[h];
    float bacc = bb2[0];
#pragma unroll
    for (int hh = 0; hh < 8; hh++) {
        float hwv = __shfl_sync(FULL, hw, hh);
        float hbv = __shfl_sync(FULL, hb, hh);
        kacc = fmaf(hwv, w2[hh * CC + h], kacc);
        bacc = fmaf(hbv, bw2[hh], bacc);
    }
    float kc   = tanh_approx(kacc);
    float bias = tanh_approx(bacc);          // lane-uniform

    float k0 = __shfl_sync(FULL, kc, 0);
    float k1 = __shfl_sync(FULL, kc, 1);
    float k2 = __shfl_sync(FULL, kc, 2);
    float k3 = __shfl_sync(FULL, kc, 3);
    float k4 = __shfl_sync(FULL, kc, 4);
    float k5 = __shfl_sync(FULL, kc, 5);
    float k6 = __shfl_sync(FULL, kc, 6);
    float k7 = __shfl_sync(FULL, kc, 7);

    float* orow = out + (long)b * TT;

    // ---- pipelined contraction: compute pair j while loading pair j+2 ----
#pragma unroll
    for (int j = 0; j < 16; j += 2) {
        float4 n0a, n0b, n1a, n1b;
        if (j + 2 < 16) {
            int u0 = tid + 128 * (j + 2);
            int u1 = tid + 128 * (j + 3);
            n0a = __ldcs(&xrow[u0 * 2]); n0b = __ldcs(&xrow[u0 * 2 + 1]);
            n1a = __ldcs(&xrow[u1 * 2]); n1b = __ldcs(&xrow[u1 * 2 + 1]);
        }

        float ya = bias;
        ya = fmaf(p0a.x, k0, ya); ya = fmaf(p0a.y, k1, ya);
        ya = fmaf(p0a.z, k2, ya); ya = fmaf(p0a.w, k3, ya);
        ya = fmaf(p0b.x, k4, ya); ya = fmaf(p0b.y, k5, ya);
        ya = fmaf(p0b.z, k6, ya); ya = fmaf(p0b.w, k7, ya);

        float yb = bias;
        yb = fmaf(p1a.x, k0, yb); yb = fmaf(p1a.y, k1, yb);
        yb = fmaf(p1a.z, k2, yb); yb = fmaf(p1a.w, k3, yb);
        yb = fmaf(p1b.x, k4, yb); yb = fmaf(p1b.y, k5, yb);
        yb = fmaf(p1b.z, k6, yb); yb = fmaf(p1b.w, k7, yb);

        __stcs(&orow[tid + 128 * j],       elu(ya));
        __stcs(&orow[tid + 128 * (j + 1)], elu(yb));

        p0a = n0a; p0b = n0b;
        p1a = n1a; p1b = n1b;
    }
}

extern "C" void kernel_launch(void* const* d_in, const int* in_sizes, int n_in,
                              void* d_out, int out_size) {
    const float* x      = (const float*)d_in[0];
    const float* attrs  = (const float*)d_in[1];
    const float* w1     = (const float*)d_in[2];
    const float* b1     = (const float*)d_in[3];
    const float* w2     = (const float*)d_in[4];
    const float* b2     = (const float*)d_in[5];
    const float* bw1    = (const float*)d_in[6];
    const float* bb1    = (const float*)d_in[7];
    const float* bw2    = (const float*)d_in[8];
    const float* bb2    = (const float*)d_in[9];
    const float* mask_a = (const float*)d_in[10];
    const float* mask_h = (const float*)d_in[11];
    float* out = (float*)d_out;

    fused_kernel<<<BB, 128>>>(x, attrs, w1, b1, w2, b2,
                              bw1, bb1, bw2, bb2,
                              mask_a, mask_h, out);
}

// round 12
// speedup vs baseline: 5.0132x; 1.0011x over previous
#include <cuda_runtime.h>
#include <math.h>

#define BB 2048
#define TT 2048
#define CC 8
#define AA 27
#define HH 8

__device__ __forceinline__ float tanh_approx(float v) {
    float r;
    asm("tanh.approx.f32 %0, %1;" : "=f"(r) : "f"(v));
    return r;
}

__device__ __forceinline__ float elu(float y) {
    return (y > 0.0f) ? y : expm1f(y);
}

// Fused. One block of 256 threads handles TWO batch rows.
// Warp 0 computes row b0's MLP, warp 1 computes row b1's (warp-cooperative,
// shfl-based) into smem -> exactly ONE MLP instance per row. One barrier.
// Then all warps stream both rows (8 t's/thread/row, pair-ahead pipeline).
// Grid = 1024 blocks: fully resident in a single wave.
__global__ void __launch_bounds__(256) fused_kernel(
    const float* __restrict__ x,
    const float* __restrict__ attrs,
    const float* __restrict__ w1,  const float* __restrict__ b1,
    const float* __restrict__ w2,  const float* __restrict__ b2,
    const float* __restrict__ bw1, const float* __restrict__ bb1,
    const float* __restrict__ bw2, const float* __restrict__ bb2,
    const float* __restrict__ mask_a,
    const float* __restrict__ mask_h,
    float* __restrict__ out)
{
    __shared__ float sk[2][CC];
    __shared__ float sb[2];

    int tid  = threadIdx.x;
    int wid  = tid >> 5;
    int lane = tid & 31;
    int b0   = blockIdx.x * 2;

    // ---- issue row0's first two load-pairs before the MLP (independent) ----
    const float4* xr0 = (const float4*)(x + (long)b0 * TT * CC);
    float4 p0a = __ldcs(&xr0[tid * 2]);
    float4 p0b = __ldcs(&xr0[tid * 2 + 1]);
    float4 p1a = __ldcs(&xr0[(tid + 256) * 2]);
    float4 p1b = __ldcs(&xr0[(tid + 256) * 2 + 1]);

    // ---- warps 0/1: warp-cooperative MLP, one row each ----
    if (wid < 2) {
        const unsigned FULL = 0xFFFFFFFFu;
        int b = b0 + wid;
        int h = lane & 7;
        int g = lane >> 3;

        float hw = 0.0f, hb = 0.0f;
#pragma unroll
        for (int s = 0; s < 7; s++) {
            int i = g + 4 * s;
            if (i < AA) {
                float ai = attrs[b * AA + i] * mask_a[b * AA + i];
                hw = fmaf(ai, w1[i * HH + h], hw);
                hb = fmaf(ai, bw1[i * HH + h], hb);
            }
        }
        hw += __shfl_xor_sync(FULL, hw, 8);
        hw += __shfl_xor_sync(FULL, hw, 16);
        hb += __shfl_xor_sync(FULL, hb, 8);
        hb += __shfl_xor_sync(FULL, hb, 16);

        float m = mask_h[b * HH + h];
        hw = fmaxf(hw + b1[h], 0.0f) * m;
        hb = fmaxf(hb + bb1[h], 0.0f) * m;

        float kacc = b2[h];
        float bacc = bb2[0];
#pragma unroll
        for (int hh = 0; hh < 8; hh++) {
            float hwv = __shfl_sync(FULL, hw, hh);
            float hbv = __shfl_sync(FULL, hb, hh);
            kacc = fmaf(hwv, w2[hh * CC + h], kacc);
            bacc = fmaf(hbv, bw2[hh], bacc);
        }
        float kc = tanh_approx(kacc);
        if (lane < 8)  sk[wid][lane] = kc;
        if (lane == 0) sb[wid] = tanh_approx(bacc);
    }
    __syncthreads();

    // ---- stream both rows ----
#pragma unroll
    for (int r = 0; r < 2; r++) {
        int b = b0 + r;
        const float4* xrow = (const float4*)(x + (long)b * TT * CC);
        float* orow = out + (long)b * TT;

        float k0 = sk[r][0], k1 = sk[r][1], k2 = sk[r][2], k3 = sk[r][3];
        float k4 = sk[r][4], k5 = sk[r][5], k6 = sk[r][6], k7 = sk[r][7];
        float bias = sb[r];

        float4 q0a, q0b, q1a, q1b;
        if (r == 0) {
            q0a = p0a; q0b = p0b; q1a = p1a; q1b = p1b;
        } else {
            q0a = __ldcs(&xrow[tid * 2]);
            q0b = __ldcs(&xrow[tid * 2 + 1]);
            q1a = __ldcs(&xrow[(tid + 256) * 2]);
            q1b = __ldcs(&xrow[(tid + 256) * 2 + 1]);
        }

#pragma unroll
        for (int j = 0; j < 8; j += 2) {
            float4 n0a, n0b, n1a, n1b;
            if (j + 2 < 8) {
                int u0 = tid + 256 * (j + 2);
                int u1 = tid + 256 * (j + 3);
                n0a = __ldcs(&xrow[u0 * 2]); n0b = __ldcs(&xrow[u0 * 2 + 1]);
                n1a = __ldcs(&xrow[u1 * 2]); n1b = __ldcs(&xrow[u1 * 2 + 1]);
            }

            float ya = bias;
            ya = fmaf(q0a.x, k0, ya); ya = fmaf(q0a.y, k1, ya);
            ya = fmaf(q0a.z, k2, ya); ya = fmaf(q0a.w, k3, ya);
            ya = fmaf(q0b.x, k4, ya); ya = fmaf(q0b.y, k5, ya);
            ya = fmaf(q0b.z, k6, ya); ya = fmaf(q0b.w, k7, ya);

            float yb = bias;
            yb = fmaf(q1a.x, k0, yb); yb = fmaf(q1a.y, k1, yb);
            yb = fmaf(q1a.z, k2, yb); yb = fmaf(q1a.w, k3, yb);
            yb = fmaf(q1b.x, k4, yb); yb = fmaf(q1b.y, k5, yb);
            yb = fmaf(q1b.z, k6, yb); yb = fmaf(q1b.w, k7, yb);

            __stcs(&orow[tid + 256 * j],       elu(ya));
            __stcs(&orow[tid + 256 * (j + 1)], elu(yb));

            q0a = n0a; q0b = n0b;
            q1a = n1a; q1b = n1b;
        }
    }
}

extern "C" void kernel_launch(void* const* d_in, const int* in_sizes, int n_in,
                              void* d_out, int out_size) {
    const float* x      = (const float*)d_in[0];
    const float* attrs  = (const float*)d_in[1];
    const float* w1     = (const float*)d_in[2];
    const float* b1     = (const float*)d_in[3];
    const float* w2     = (const float*)d_in[4];
    const float* b2     = (const float*)d_in[5];
    const float* bw1    = (const float*)d_in[6];
    const float* bb1    = (const float*)d_in[7];
    const float* bw2    = (const float*)d_in[8];
    const float* bb2    = (const float*)d_in[9];
    const float* mask_a = (const float*)d_in[10];
    const float* mask_h = (const float*)d_in[11];
    float* out = (float*)d_out;

    fused_kernel<<<BB / 2, 256>>>(x, attrs, w1, b1, w2, b2,
                                  bw1, bb1, bw2, bb2,
                                  mask_a, mask_h, out);
}